// round 6
// baseline (speedup 1.0000x reference)
#include <cuda_runtime.h>
#include <cuda_bf16.h>
#include <cstdint>

// AdaBoost fused classifier via legacy mma.sync TF32 (base-ISA, works on
// plain sm_103 target — tcgen05 needs the 'a' feature set the harness
// doesn't enable).
//   logits[N,E] = x[N,F] @ W[E,F]^T + b
//   pred = (logit > 0);  acc = sum_e pred * trunc(alpha_e);  out = sign(acc)
// Single-pass tf32 MMA; any |logit| < TAU is recomputed exactly in fp32
// (same serial arithmetic that passed with rel_err 0.0 in earlier rounds).
//
// 256 threads, BM=128 x BN=256(=E) x BK=32, warp grid 2(m) x 4(n),
// warp tile 64x64 via m16n8k8.tf32. Smem rows padded to 36 words so all
// fragment LDS.32 are bank-conflict-free. Register prefetch of next chunk.

#define F_DIM 512
#define E_DIM 256
#define BM 128
#define BK 32
#define NCHUNK (F_DIM / BK)
#define TAU 4e-3f

#define A_STRIDE 36   // words per A row (32 + 4 pad)
#define B_STRIDE 36   // words per B row
#define A_WORDS (BM * A_STRIDE)        // 4608
#define B_WORDS (E_DIM * B_STRIDE)     // 9216
#define DSMEM_BYTES ((A_WORDS + B_WORDS) * 4)

static __device__ __forceinline__ uint32_t to_tf32(float x) {
    uint32_t r;
    asm("cvt.rna.tf32.f32 %0, %1;" : "=r"(r) : "f"(x));
    return r;
}

#define MMA_TF32(c, a, b)                                                  \
    asm volatile(                                                          \
        "mma.sync.aligned.m16n8k8.row.col.f32.tf32.tf32.f32 "              \
        "{%0,%1,%2,%3}, {%4,%5,%6,%7}, {%8,%9}, {%0,%1,%2,%3};"            \
        : "+f"((c)[0]), "+f"((c)[1]), "+f"((c)[2]), "+f"((c)[3])           \
        : "r"((a)[0]), "r"((a)[1]), "r"((a)[2]), "r"((a)[3]),              \
          "r"((b)[0]), "r"((b)[1]))

__global__ __launch_bounds__(256, 1)
void adaboost_mma_kernel(const float* __restrict__ x,
                         const float* __restrict__ Wm,
                         const float* __restrict__ bvec,
                         const float* __restrict__ alphas,
                         float* __restrict__ out) {
    extern __shared__ uint32_t smem[];
    uint32_t* As = smem;             // [128][36] tf32
    uint32_t* Bs = smem + A_WORDS;   // [256][36] tf32

    __shared__ float s_b[E_DIM];
    __shared__ float s_ta[E_DIM];
    __shared__ float psum[BM][4];

    const int tid  = threadIdx.x;
    const int wid  = tid >> 5;
    const int lane = tid & 31;
    const int g    = lane >> 2;    // group id (row within 8)
    const int tg   = lane & 3;     // thread-in-group
    const int wm   = wid & 1;      // warp m index (2)
    const int wn   = wid >> 1;     // warp n index (4)
    const int m0   = blockIdx.x * BM;

    s_b[tid]  = bvec[tid];
    s_ta[tid] = truncf(alphas[tid]);

    float acc[4][8][4];
#pragma unroll
    for (int i = 0; i < 4; i++)
#pragma unroll
        for (int j = 0; j < 8; j++)
#pragma unroll
            for (int r = 0; r < 4; r++) acc[i][j][r] = 0.0f;

    // ---- prefetch chunk 0 ----
    float4 pa[4], pb[8];
#pragma unroll
    for (int l = 0; l < 4; l++) {
        int idx4 = tid + 256 * l;
        int row = idx4 >> 3, q = idx4 & 7;
        pa[l] = *reinterpret_cast<const float4*>(x + (size_t)(m0 + row) * F_DIM + q * 4);
    }
#pragma unroll
    for (int l = 0; l < 8; l++) {
        int idx4 = tid + 256 * l;
        int n = idx4 >> 3, q = idx4 & 7;
        pb[l] = *reinterpret_cast<const float4*>(Wm + (size_t)n * F_DIM + q * 4);
    }

    for (int t = 0; t < NCHUNK; t++) {
        // ---- commit prefetched chunk to smem as tf32 ----
#pragma unroll
        for (int l = 0; l < 4; l++) {
            int idx4 = tid + 256 * l;
            int row = idx4 >> 3, q = idx4 & 7;
            uint4 v;
            v.x = to_tf32(pa[l].x); v.y = to_tf32(pa[l].y);
            v.z = to_tf32(pa[l].z); v.w = to_tf32(pa[l].w);
            *reinterpret_cast<uint4*>(&As[row * A_STRIDE + q * 4]) = v;
        }
#pragma unroll
        for (int l = 0; l < 8; l++) {
            int idx4 = tid + 256 * l;
            int n = idx4 >> 3, q = idx4 & 7;
            uint4 v;
            v.x = to_tf32(pb[l].x); v.y = to_tf32(pb[l].y);
            v.z = to_tf32(pb[l].z); v.w = to_tf32(pb[l].w);
            *reinterpret_cast<uint4*>(&Bs[n * B_STRIDE + q * 4]) = v;
        }
        __syncthreads();

        // ---- prefetch next chunk (overlaps compute) ----
        if (t + 1 < NCHUNK) {
            int k0n = (t + 1) * BK;
#pragma unroll
            for (int l = 0; l < 4; l++) {
                int idx4 = tid + 256 * l;
                int row = idx4 >> 3, q = idx4 & 7;
                pa[l] = *reinterpret_cast<const float4*>(
                    x + (size_t)(m0 + row) * F_DIM + k0n + q * 4);
            }
#pragma unroll
            for (int l = 0; l < 8; l++) {
                int idx4 = tid + 256 * l;
                int n = idx4 >> 3, q = idx4 & 7;
                pb[l] = *reinterpret_cast<const float4*>(
                    Wm + (size_t)n * F_DIM + k0n + q * 4);
            }
        }

        // ---- compute: 4 k-steps of m16n8k8 ----
#pragma unroll
        for (int ks = 0; ks < 4; ks++) {
            uint32_t afr[4][4];
#pragma unroll
            for (int mt = 0; mt < 4; mt++) {
                int rb = wm * 64 + mt * 16;
                int kc = ks * 8 + tg;
                afr[mt][0] = As[(rb + g)     * A_STRIDE + kc];
                afr[mt][1] = As[(rb + g + 8) * A_STRIDE + kc];
                afr[mt][2] = As[(rb + g)     * A_STRIDE + kc + 4];
                afr[mt][3] = As[(rb + g + 8) * A_STRIDE + kc + 4];
            }
            uint32_t bfr[8][2];
#pragma unroll
            for (int nt = 0; nt < 8; nt++) {
                int n = wn * 64 + nt * 8 + g;
                int kc = ks * 8 + tg;
                bfr[nt][0] = Bs[n * B_STRIDE + kc];
                bfr[nt][1] = Bs[n * B_STRIDE + kc + 4];
            }
#pragma unroll
            for (int mt = 0; mt < 4; mt++)
#pragma unroll
                for (int nt = 0; nt < 8; nt++)
                    MMA_TF32(acc[mt][nt], afr[mt], bfr[nt]);
        }
        __syncthreads();
    }

    // ---------------- fused epilogue ----------------
    // acc[mt][nt]: c0,c1 -> (row rb+g,   cols cb+2tg, +1)
    //              c2,c3 -> (row rb+g+8, cols cb+2tg, +1)
#pragma unroll
    for (int mt = 0; mt < 4; mt++) {
#pragma unroll
        for (int half = 0; half < 2; half++) {
            int rowl = wm * 64 + mt * 16 + g + half * 8;
            float s = 0.0f;
#pragma unroll
            for (int nt = 0; nt < 8; nt++) {
#pragma unroll
                for (int j = 0; j < 2; j++) {
                    int col = wn * 64 + nt * 8 + 2 * tg + j;
                    float logit = acc[mt][nt][half * 2 + j] + s_b[col];
                    if (fabsf(logit) < TAU) {
                        // exact fp32 recompute of this dot product
                        const float* xr = x + (size_t)(m0 + rowl) * F_DIM;
                        const float* wr = Wm + (size_t)col * F_DIM;
                        float a = 0.0f;
#pragma unroll 8
                        for (int f = 0; f < F_DIM; f++)
                            a = fmaf(__ldg(xr + f), __ldg(wr + f), a);
                        logit = a + s_b[col];
                    }
                    if (logit > 0.0f) s += s_ta[col];
                }
            }
            // reduce over the 4 tg threads (same rows, different cols)
            s += __shfl_xor_sync(0xffffffffu, s, 1);
            s += __shfl_xor_sync(0xffffffffu, s, 2);
            if (tg == 0) psum[rowl][wn] = s;
        }
    }
    __syncthreads();

    if (tid < BM) {
        float s = psum[tid][0] + psum[tid][1] + psum[tid][2] + psum[tid][3];
        out[m0 + tid] = (s > 0.0f) ? 1.0f : ((s < 0.0f) ? -1.0f : 0.0f);
    }
}

extern "C" void kernel_launch(void* const* d_in, const int* in_sizes, int n_in,
                              void* d_out, int out_size) {
    const float* x      = (const float*)d_in[0];   // [N, F]
    const float* Wm     = (const float*)d_in[1];   // [E, F]
    const float* bvec   = (const float*)d_in[2];   // [E]
    const float* alphas = (const float*)d_in[3];   // [E]
    float* out = (float*)d_out;                    // [N]

    const int E = in_sizes[2];         // 256
    const int F = in_sizes[1] / E;     // 512
    const int N = in_sizes[0] / F;     // 131072

    (void)E; (void)F;
    cudaFuncSetAttribute(adaboost_mma_kernel,
                         cudaFuncAttributeMaxDynamicSharedMemorySize, DSMEM_BYTES);

    dim3 grid(N / BM);
    dim3 block(256);
    adaboost_mma_kernel<<<grid, block, DSMEM_BYTES>>>(x, Wm, bvec, alphas, out);
}

// round 7
// speedup vs baseline: 5.5086x; 5.5086x over previous
#include <cuda_runtime.h>
#include <cuda_bf16.h>
#include <cstdint>

// AdaBoost fused classifier via legacy mma.sync TF32 (base-ISA sm_103).
//   logits[N,E] = x[N,F] @ W[E,F]^T + b
//   pred = (logit > 0); acc = sum_e pred*trunc(alpha); out = sign(acc)
// Borderline logits (|logit| < TAU) recomputed exactly in fp32 via a
// warp-cooperative rescue queue (coalesced, parallel).
//
// W pre-converted to tf32 once into __device__ scratch -> B tiles stream
// via cp.async. BM=64 x BN=256(=E) x BK=32, 256 thr, 2 CTAs/SM, ping-pong
// smem, one __syncthreads per chunk. Warp tile 32x64 (m16n8k8.tf32).

#define F_DIM 512
#define E_DIM 256
#define BM 64
#define BK 32
#define NCHUNK (F_DIM / BK)
#define TAU 4e-3f
#define QCAP 1024

#define SA 36                         // padded row stride (words)
#define A_WORDS (BM * SA)             // 2304
#define B_WORDS (E_DIM * SA)          // 9216
#define DSMEM_BYTES ((2 * A_WORDS + 2 * B_WORDS) * 4)   // 92160

__device__ uint32_t g_Wtf32[E_DIM * F_DIM];   // pre-converted W (tf32 bits)

static __device__ __forceinline__ uint32_t to_tf32(float x) {
    uint32_t r;
    asm("cvt.rna.tf32.f32 %0, %1;" : "=r"(r) : "f"(x));
    return r;
}

static __device__ __forceinline__ uint32_t smem_u32(const void* p) {
    uint32_t a;
    asm("{ .reg .u64 t; cvta.to.shared.u64 t, %1; cvt.u32.u64 %0, t; }"
        : "=r"(a) : "l"(p));
    return a;
}

#define CP_ASYNC16(dst, src) \
    asm volatile("cp.async.ca.shared.global [%0], [%1], 16;" \
                 :: "r"(dst), "l"(src) : "memory")
#define CP_COMMIT() asm volatile("cp.async.commit_group;" ::: "memory")
#define CP_WAIT_ALL() asm volatile("cp.async.wait_group 0;" ::: "memory")

#define MMA_TF32(c, a, b)                                                  \
    asm volatile(                                                          \
        "mma.sync.aligned.m16n8k8.row.col.f32.tf32.tf32.f32 "              \
        "{%0,%1,%2,%3}, {%4,%5,%6,%7}, {%8,%9}, {%0,%1,%2,%3};"            \
        : "+f"((c)[0]), "+f"((c)[1]), "+f"((c)[2]), "+f"((c)[3])           \
        : "r"((a)[0]), "r"((a)[1]), "r"((a)[2]), "r"((a)[3]),              \
          "r"((b)[0]), "r"((b)[1]))

// ---- prep: convert W to tf32 bits (runs once per launch, ~0.5MB) ----
__global__ void prep_kernel(const float* __restrict__ Wm) {
    int i = (blockIdx.x * blockDim.x + threadIdx.x) * 4;
    float4 v = *reinterpret_cast<const float4*>(Wm + i);
    uint4 o;
    o.x = to_tf32(v.x); o.y = to_tf32(v.y);
    o.z = to_tf32(v.z); o.w = to_tf32(v.w);
    *reinterpret_cast<uint4*>(g_Wtf32 + i) = o;
}

__global__ __launch_bounds__(256, 2)
void adaboost_mma_kernel(const float* __restrict__ x,
                         const float* __restrict__ Wm,
                         const float* __restrict__ bvec,
                         const float* __restrict__ alphas,
                         float* __restrict__ out) {
    extern __shared__ uint32_t sm[];
    uint32_t* As = sm;                       // [2][64][SA]
    uint32_t* Bs = sm + 2 * A_WORDS;         // [2][256][SA]

    __shared__ float s_b[E_DIM];
    __shared__ float s_ta[E_DIM];
    __shared__ float psum[BM][4];
    __shared__ float s_rsum[BM];
    __shared__ int s_nresc;
    __shared__ uint32_t s_q[QCAP];

    const int tid  = threadIdx.x;
    const int wid  = tid >> 5;
    const int lane = tid & 31;
    const int g    = lane >> 2;
    const int tg   = lane & 3;
    const int wm   = wid & 1;      // 2 warp-rows
    const int wn   = wid >> 1;     // 4 warp-cols
    const int m0   = blockIdx.x * BM;

    s_b[tid]  = bvec[tid];
    s_ta[tid] = truncf(alphas[tid]);
    if (tid < BM) s_rsum[tid] = 0.0f;
    if (tid == 0) s_nresc = 0;

    const uint32_t As_u = smem_u32(As);
    const uint32_t Bs_u = smem_u32(Bs);

    float acc[2][8][4];
#pragma unroll
    for (int i = 0; i < 2; i++)
#pragma unroll
        for (int j = 0; j < 8; j++)
#pragma unroll
            for (int r = 0; r < 4; r++) acc[i][j][r] = 0.0f;

    // per-thread A mapping: 2 float4 per chunk
    const int a_row0 = tid >> 2;           // 0..63
    const int a_q0   = (tid & 3) * 2;      // 0,2,4,6  (two float4 each)

    // ---- prologue: chunk 0 ----
    {
        // B chunk 0 via cp.async
#pragma unroll
        for (int l = 0; l < 8; l++) {
            int idx = tid + 256 * l;
            int n = idx >> 3, q = idx & 7;
            CP_ASYNC16(Bs_u + (n * SA + q * 4) * 4,
                       (const char*)(g_Wtf32 + (size_t)n * F_DIM + q * 4));
        }
        CP_COMMIT();
        // A chunk 0: LDG -> cvt -> STS
#pragma unroll
        for (int h = 0; h < 2; h++) {
            float4 v = *reinterpret_cast<const float4*>(
                x + (size_t)(m0 + a_row0) * F_DIM + (a_q0 + h) * 4);
            uint4 o;
            o.x = to_tf32(v.x); o.y = to_tf32(v.y);
            o.z = to_tf32(v.z); o.w = to_tf32(v.w);
            *reinterpret_cast<uint4*>(&As[a_row0 * SA + (a_q0 + h) * 4]) = o;
        }
    }

    // ---- main loop ----
    for (int t = 0; t < NCHUNK; t++) {
        const int p = t & 1;
        CP_WAIT_ALL();
        __syncthreads();   // buffers p ready; buffers p^1 free everywhere

        float4 pa[2];
        if (t + 1 < NCHUNK) {
            const int kn = (t + 1) * BK;
            // B(t+1) -> Bs[p^1]
#pragma unroll
            for (int l = 0; l < 8; l++) {
                int idx = tid + 256 * l;
                int n = idx >> 3, q = idx & 7;
                CP_ASYNC16(Bs_u + ((p ^ 1) * B_WORDS + n * SA + q * 4) * 4,
                           (const char*)(g_Wtf32 + (size_t)n * F_DIM + kn + q * 4));
            }
            CP_COMMIT();
            // A(t+1) -> regs
#pragma unroll
            for (int h = 0; h < 2; h++)
                pa[h] = *reinterpret_cast<const float4*>(
                    x + (size_t)(m0 + a_row0) * F_DIM + kn + (a_q0 + h) * 4);
        }

        // ---- compute on buffers p ----
        const uint32_t* Ap = As + p * A_WORDS;
        const uint32_t* Bp = Bs + p * B_WORDS;
#pragma unroll
        for (int ks = 0; ks < 4; ks++) {
            const int kc = ks * 8 + tg;
            uint32_t afr[2][4];
#pragma unroll
            for (int mt = 0; mt < 2; mt++) {
                int rb = wm * 32 + mt * 16;
                afr[mt][0] = Ap[(rb + g)     * SA + kc];
                afr[mt][1] = Ap[(rb + g + 8) * SA + kc];
                afr[mt][2] = Ap[(rb + g)     * SA + kc + 4];
                afr[mt][3] = Ap[(rb + g + 8) * SA + kc + 4];
            }
            uint32_t bfr[8][2];
#pragma unroll
            for (int nt = 0; nt < 8; nt++) {
                int n = wn * 64 + nt * 8 + g;
                bfr[nt][0] = Bp[n * SA + kc];
                bfr[nt][1] = Bp[n * SA + kc + 4];
            }
#pragma unroll
            for (int mt = 0; mt < 2; mt++)
#pragma unroll
                for (int nt = 0; nt < 8; nt++)
                    MMA_TF32(acc[mt][nt], afr[mt], bfr[nt]);
        }

        // ---- commit A(t+1) to smem ----
        if (t + 1 < NCHUNK) {
            uint32_t* An = As + (p ^ 1) * A_WORDS;
#pragma unroll
            for (int h = 0; h < 2; h++) {
                uint4 o;
                o.x = to_tf32(pa[h].x); o.y = to_tf32(pa[h].y);
                o.z = to_tf32(pa[h].z); o.w = to_tf32(pa[h].w);
                *reinterpret_cast<uint4*>(&An[a_row0 * SA + (a_q0 + h) * 4]) = o;
            }
        }
    }

    // ---------------- epilogue ----------------
#pragma unroll
    for (int mt = 0; mt < 2; mt++) {
#pragma unroll
        for (int half = 0; half < 2; half++) {
            int rowl = wm * 32 + mt * 16 + g + half * 8;
            float s = 0.0f;
#pragma unroll
            for (int nt = 0; nt < 8; nt++) {
#pragma unroll
                for (int j = 0; j < 2; j++) {
                    int col = wn * 64 + nt * 8 + 2 * tg + j;
                    float logit = acc[mt][nt][half * 2 + j] + s_b[col];
                    if (fabsf(logit) < TAU) {
                        int qi = atomicAdd(&s_nresc, 1);
                        if (qi < QCAP) {
                            s_q[qi] = ((uint32_t)rowl << 8) | (uint32_t)col;
                        } else {
                            // overflow fallback: exact serial recompute
                            const float* xr = x + (size_t)(m0 + rowl) * F_DIM;
                            const float* wr = Wm + (size_t)col * F_DIM;
                            float a = 0.0f;
                            for (int f = 0; f < F_DIM; f++)
                                a = fmaf(__ldg(xr + f), __ldg(wr + f), a);
                            if (a + s_b[col] > 0.0f) s += s_ta[col];
                        }
                    } else if (logit > 0.0f) {
                        s += s_ta[col];
                    }
                }
            }
            s += __shfl_xor_sync(0xffffffffu, s, 1);
            s += __shfl_xor_sync(0xffffffffu, s, 2);
            if (tg == 0) psum[rowl][wn] = s;
        }
    }
    __syncthreads();

    // ---- warp-cooperative rescue: exact fp32 dot per queue entry ----
    {
        const int nresc = min(s_nresc, QCAP);
        for (int i = wid; i < nresc; i += 8) {
            uint32_t ent = s_q[i];
            int rowl = (int)(ent >> 8);
            int col  = (int)(ent & 0xFF);
            const float* xr = x + (size_t)(m0 + rowl) * F_DIM;
            const float* wr = Wm + (size_t)col * F_DIM;
            float a0 = 0.0f, a1 = 0.0f;
#pragma unroll
            for (int j = 0; j < 16; j += 2) {
                a0 = fmaf(__ldg(xr + j * 32 + lane), __ldg(wr + j * 32 + lane), a0);
                a1 = fmaf(__ldg(xr + (j + 1) * 32 + lane), __ldg(wr + (j + 1) * 32 + lane), a1);
            }
            float a = a0 + a1;
#pragma unroll
            for (int o = 16; o > 0; o >>= 1)
                a += __shfl_xor_sync(0xffffffffu, a, o);
            if (lane == 0 && a + s_b[col] > 0.0f)
                atomicAdd(&s_rsum[rowl], s_ta[col]);
        }
    }
    __syncthreads();

    if (tid < BM) {
        float s = psum[tid][0] + psum[tid][1] + psum[tid][2] + psum[tid][3]
                + s_rsum[tid];
        out[m0 + tid] = (s > 0.0f) ? 1.0f : ((s < 0.0f) ? -1.0f : 0.0f);
    }
}

extern "C" void kernel_launch(void* const* d_in, const int* in_sizes, int n_in,
                              void* d_out, int out_size) {
    const float* x      = (const float*)d_in[0];   // [N, F]
    const float* Wm     = (const float*)d_in[1];   // [E, F]
    const float* bvec   = (const float*)d_in[2];   // [E]
    const float* alphas = (const float*)d_in[3];   // [E]
    float* out = (float*)d_out;                    // [N]

    const int E = in_sizes[2];         // 256
    const int F = in_sizes[1] / E;     // 512
    const int N = in_sizes[0] / F;     // 131072

    (void)E; (void)F;
    prep_kernel<<<(E_DIM * F_DIM) / (256 * 4), 256>>>(Wm);

    cudaFuncSetAttribute(adaboost_mma_kernel,
                         cudaFuncAttributeMaxDynamicSharedMemorySize, DSMEM_BYTES);
    adaboost_mma_kernel<<<N / BM, 256, DSMEM_BYTES>>>(x, Wm, bvec, alphas, out);
}